// round 9
// baseline (speedup 1.0000x reference)
#include <cuda_runtime.h>
#include <cstdint>

#define BATCH 32
#define CCH 256
#define HWSZ 3136
#define CHWSZ (CCH*HWSZ)
#define NPIX (BATCH*HWSZ)        // 100352
#define PW 58
#define PADHW (PW*PW)            // 3364
#define PPB (128*PADHW)          // u16 cells per batch image (128 channel-pairs)
#define NPR ((size_t)BATCH*(size_t)PPB)   // u16 cells per plane
#define EPSF 1e-5f

#define MT 128
#define NTHR 512
#define NGRID (NPIX/MT)          // 784
#define PA 144                   // A smem pitch bytes (128 data + 16 pad)
#define PB 144

// dynamic smem layout
#define OB 0                     // B: 2 x 36864
#define OA 73728                 // A: 2 x 18432
#define OBASE 110592             // int[128]
#define OOB   111104             // int[128]
#define OBN   111616             // float[5][256]
#define DSM   116736

// ---------------- device globals ----------------
__device__ unsigned short g_d0[NPR];   // digit planes, channel-pair-interleaved
__device__ unsigned short g_d1[NPR];
__device__ unsigned short g_d2[NPR];
__device__ unsigned short g_ri8[NPR];  // conv1 output levels (uint4), pair-interleaved
__device__ float g_sc[(size_t)NPIX*CCH];
__device__ char  g_wb1[256*2304];
__device__ char  g_wb2[256*2304];
__device__ char  g_wbs[256*256];
__device__ unsigned g_maxbits[4];

// ---------------- helpers ----------------
__device__ __forceinline__ uint32_t smem_u32(const void* p) {
    uint32_t a;
    asm("{ .reg .u64 t; cvta.to.shared.u64 t, %1; cvt.u32.u64 %0, t; }" : "=r"(a) : "l"(p));
    return a;
}
__device__ __forceinline__ void ldsm4(uint32_t* r, uint32_t a) {
    asm volatile("ldmatrix.sync.aligned.m8n8.x4.shared.b16 {%0,%1,%2,%3}, [%4];"
                 : "=r"(r[0]), "=r"(r[1]), "=r"(r[2]), "=r"(r[3]) : "r"(a));
}
__device__ __forceinline__ void mma16832(int* c, const uint32_t* a, const uint32_t* b) {
    asm volatile("mma.sync.aligned.m16n8k32.row.col.s32.s8.s8.s32 "
                 "{%0,%1,%2,%3}, {%4,%5,%6,%7}, {%8,%9}, {%0,%1,%2,%3};"
                 : "+r"(c[0]), "+r"(c[1]), "+r"(c[2]), "+r"(c[3])
                 : "r"(a[0]), "r"(a[1]), "r"(a[2]), "r"(a[3]), "r"(b[0]), "r"(b[1]));
}
__device__ __forceinline__ void cpa16(uint32_t d, const void* s) {
    asm volatile("cp.async.ca.shared.global [%0], [%1], 16;" :: "r"(d), "l"(s));
}
__device__ __forceinline__ void cpcommit() { asm volatile("cp.async.commit_group;"); }
__device__ __forceinline__ void cpwait0()  { asm volatile("cp.async.wait_group 0;"); }

// ---------------- prep kernels ----------------
__global__ void zero_max_kernel() { if (threadIdx.x < 4) g_maxbits[threadIdx.x] = 0u; }

__global__ void absmax_kernel(const float* __restrict__ w, int n, int slot) {
    __shared__ unsigned sm[256];
    unsigned m = 0u;
    for (int i = blockIdx.x * blockDim.x + threadIdx.x; i < n; i += gridDim.x * blockDim.x)
        m = max(m, __float_as_uint(fabsf(w[i])));
    sm[threadIdx.x] = m;
    __syncthreads();
    for (int s = 128; s > 0; s >>= 1) {
        if (threadIdx.x < s) sm[threadIdx.x] = max(sm[threadIdx.x], sm[threadIdx.x + s]);
        __syncthreads();
    }
    if (threadIdx.x == 0) atomicMax(&g_maxbits[slot], sm[0]);
}

// integer levels as s8; 3x3 K-order: k = tap*256 + ci
__global__ void prepw3_kernel(const float* __restrict__ w, char* __restrict__ dst, int slot) {
    int idx = blockIdx.x * blockDim.x + threadIdx.x;   // 256*2304
    int n = idx / 2304, k = idx - n * 2304;
    int tap = k >> 8, ci = k & 255;
    float s = __uint_as_float(g_maxbits[slot]) / 7.0f;
    float q = rintf(fminf(fmaxf(w[n * 2304 + ci * 9 + tap] / s, -7.0f), 7.0f));
    dst[n * 2304 + k] = (char)(int)q;
}
__global__ void prepw1_kernel(const float* __restrict__ w, char* __restrict__ dst, int slot) {
    int idx = blockIdx.x * blockDim.x + threadIdx.x;   // 256*256
    float s = __uint_as_float(g_maxbits[slot]) / 7.0f;
    float q = rintf(fminf(fmaxf(w[idx] / s, -7.0f), 7.0f));
    dst[idx] = (char)(int)q;
}

// x -> 3 int8 digit planes, channel-pair-interleaved, zero border.
// x = d0/8 + d1/2^10 + d2/2^17 + eps, |eps| <= 2^-18
__global__ void splitd_kernel(const float* __restrict__ x) {
    size_t i = (size_t)blockIdx.x * blockDim.x + threadIdx.x;
    if (i >= NPR) return;
    size_t b = i / PPB;
    int r = (int)(i - b * PPB);
    int pair = r / PADHW, pix = r - pair * PADHW;
    int py = pix / PW, px = pix - py * PW;
    bool in = (py >= 1 && py <= 56 && px >= 1 && px <= 56);
    unsigned w0 = 0, w1 = 0, w2 = 0;
#pragma unroll
    for (int h = 0; h < 2; h++) {
        float v = 0.0f;
        if (in)
            v = x[b * CHWSZ + (size_t)(2 * pair + h) * HWSZ + (py - 1) * 56 + (px - 1)];
        float f0 = rintf(v * 8.0f);
        float r0 = v - f0 * 0.125f;
        float f1 = rintf(r0 * 1024.0f);
        float r1 = r0 - f1 * (1.0f / 1024.0f);
        float f2 = rintf(r1 * 131072.0f);
        w0 |= ((unsigned)(int)f0 & 0xFFu) << (h * 8);
        w1 |= ((unsigned)(int)f1 & 0xFFu) << (h * 8);
        w2 |= ((unsigned)(int)f2 & 0xFFu) << (h * 8);
    }
    g_d0[i] = (unsigned short)w0;
    g_d1[i] = (unsigned short)w1;
    g_d2[i] = (unsigned short)w2;
}

// ---------------- IMMA implicit-GEMM conv ----------------
// mode 0: shortcut (3 digit phases) -> g_sc fp32 [ch][pix]
// mode 1: conv1 (3 digit phases) -> BN1+quant -> int8 level pair-plane
// mode 2: conv2 (exact) + sc -> BN2+quant -> out fp32 NCHW
__global__ __launch_bounds__(NTHR, 1)
void gemm_kernel(const unsigned short* __restrict__ p0,
                 const unsigned short* __restrict__ p1,
                 const unsigned short* __restrict__ p2,
                 const char* __restrict__ wB,
                 int Ktot, int cps, int nsplit, int is3x3, int slot, int mode,
                 const float* __restrict__ gmm, const float* __restrict__ bt,
                 const float* __restrict__ mn,  const float* __restrict__ vr,
                 const float* __restrict__ st,
                 const float* __restrict__ scin,
                 float* __restrict__ outf, unsigned short* __restrict__ outb,
                 const float* __restrict__ stin) {
    extern __shared__ char dyn[];
    char* base = dyn;
    const uint32_t sb = smem_u32(base);
    const int tid = threadIdx.x, wid = tid >> 5, lid = tid & 31;
    int* sBase = (int*)(base + OBASE);
    int* sOb   = (int*)(base + OOB);
    float* sBN = (float*)(base + OBN);

    if (tid < MT) {
        int p = blockIdx.x * MT + tid;
        int b = p / HWSZ, rem = p - b * HWSZ;
        int y = rem / 56, x = rem - y * 56;
        sBase[tid] = b * PPB + (y + 1) * PW + (x + 1);   // pair-plane pixel base
        sOb[tid]   = b * CHWSZ + rem;
    }
    if (tid < 256) {
        sBN[tid]        = gmm[tid];
        sBN[256 + tid]  = bt[tid];
        sBN[512 + tid]  = mn[tid];
        sBN[768 + tid]  = 1.0f / sqrtf(vr[tid] + EPSF);
        sBN[1024 + tid] = st[tid];
    }
    __syncthreads();

    const int am = tid & 127;          // A row handled by this thread
    const int ag = tid >> 7;           // cell-octet group 0..3
    const int aofs = sBase[am];
    const int m0w = (wid & 3) * 32;    // warp M origin
    const int n0w = (wid >> 2) * 64;   // warp N origin
    const int NCH = nsplit * cps;
    const bool dig = (nsplit == 3);

    int acc[2][8][4];
#pragma unroll
    for (int i = 0; i < 2; i++)
#pragma unroll
        for (int j = 0; j < 8; j++)
#pragma unroll
            for (int k = 0; k < 4; k++) acc[i][j][k] = 0;

    unsigned short hreg[16];

    // prologue: chunk 0 -> buffer 0
    {
        int td = is3x3 ? (-PW - 1) : 0;
#pragma unroll
        for (int g = 0; g < 2; g++) {
            const unsigned short* src = p0 + (size_t)(ag * 8 + g * 32) * PADHW + (aofs + td);
#pragma unroll
            for (int j = 0; j < 8; j++) hreg[g * 8 + j] = src[(size_t)j * PADHW];
        }
#pragma unroll
        for (int g = 0; g < 2; g++) {
            uint4 v;
            v.x = (uint32_t)hreg[g*8+0] | ((uint32_t)hreg[g*8+1] << 16);
            v.y = (uint32_t)hreg[g*8+2] | ((uint32_t)hreg[g*8+3] << 16);
            v.z = (uint32_t)hreg[g*8+4] | ((uint32_t)hreg[g*8+5] << 16);
            v.w = (uint32_t)hreg[g*8+6] | ((uint32_t)hreg[g*8+7] << 16);
            *(uint4*)(base + OA + am * PA + g * 64 + ag * 16) = v;
        }
#pragma unroll
        for (int i = 0; i < 4; i++) {
            int idx = tid * 4 + i;
            int n = idx >> 3, seg = idx & 7;
            cpa16(sb + OB + n * PB + seg * 16, wB + (size_t)n * Ktot + seg * 16);
        }
        cpcommit();
    }

    for (int c = 0; c < NCH; c++) {
        const int cur = c & 1, nxt = cur ^ 1;
        const bool havenext = (c + 1) < NCH;
        // 1. stage A(c+1) in registers
        if (havenext) {
            int cn = c + 1, qn = cn % cps, spn = cn / cps;
            int td, ci0p;
            if (is3x3) { int tap = qn >> 1; td = (tap / 3 - 1) * PW + (tap % 3 - 1);
                         ci0p = (qn & 1) * 64; }
            else       { td = 0; ci0p = qn * 64; }
            const unsigned short* pl = (spn == 0) ? p0 : ((spn == 1) ? p1 : p2);
#pragma unroll
            for (int g = 0; g < 2; g++) {
                const unsigned short* src =
                    pl + (size_t)(ci0p + ag * 8 + g * 32) * PADHW + (aofs + td);
#pragma unroll
                for (int j = 0; j < 8; j++) hreg[g * 8 + j] = src[(size_t)j * PADHW];
            }
        }
        // 2/3. drain B(c), barrier
        cpwait0();
        __syncthreads();
        // 4. issue B(c+1)
        if (havenext) {
            int k0 = ((c + 1) % cps) * 128;
#pragma unroll
            for (int i = 0; i < 4; i++) {
                int idx = tid * 4 + i;
                int n = idx >> 3, seg = idx & 7;
                cpa16(sb + OB + nxt * 36864 + n * PB + seg * 16,
                      wB + (size_t)n * Ktot + k0 + seg * 16);
            }
        }
        cpcommit();
        // 5. MMA over buffer cur (4 k32 steps)
        {
            const uint32_t ab = sb + OA + cur * 18432;
            const uint32_t bb = sb + OB + cur * 36864;
#pragma unroll
            for (int s = 0; s < 4; s++) {
                uint32_t afr[2][4];
#pragma unroll
                for (int mi = 0; mi < 2; mi++)
                    ldsm4(afr[mi], ab + (m0w + mi * 16 + (lid & 15)) * PA
                                      + s * 32 + (lid >> 4) * 16);
                uint32_t bfr[8][2];
#pragma unroll
                for (int h = 0; h < 4; h++) {
                    uint32_t r[4];
                    ldsm4(r, bb + (n0w + h * 16 + (lid & 7) + ((lid >> 4) << 3)) * PB
                              + s * 32 + ((lid >> 3) & 1) * 16);
                    bfr[h * 2][0] = r[0]; bfr[h * 2][1] = r[1];
                    bfr[h * 2 + 1][0] = r[2]; bfr[h * 2 + 1][1] = r[3];
                }
#pragma unroll
                for (int mi = 0; mi < 2; mi++)
#pragma unroll
                    for (int ng = 0; ng < 8; ng++)
                        mma16832(acc[mi][ng], afr[mi], bfr[ng]);
            }
        }
        // 5b. digit-phase boundary: exact Horner shift acc *= 128
        if (dig && havenext && ((c + 1) % cps) == 0) {
#pragma unroll
            for (int i = 0; i < 2; i++)
#pragma unroll
                for (int j = 0; j < 8; j++)
#pragma unroll
                    for (int k = 0; k < 4; k++) acc[i][j][k] *= 128;
        }
        // 6. commit staged A(c+1)
        if (havenext) {
#pragma unroll
            for (int g = 0; g < 2; g++) {
                uint4 v;
                v.x = (uint32_t)hreg[g*8+0] | ((uint32_t)hreg[g*8+1] << 16);
                v.y = (uint32_t)hreg[g*8+2] | ((uint32_t)hreg[g*8+3] << 16);
                v.z = (uint32_t)hreg[g*8+4] | ((uint32_t)hreg[g*8+5] << 16);
                v.w = (uint32_t)hreg[g*8+6] | ((uint32_t)hreg[g*8+7] << 16);
                *(uint4*)(base + OA + nxt * 18432 + am * PA + g * 64 + ag * 16) = v;
            }
        }
    }
    __syncthreads();

    // ---- epilogue ----
    const float s = __uint_as_float(g_maxbits[slot]) / 7.0f;
    const float fac = (mode == 2) ? (s * stin[0]) : (s * (1.0f / 131072.0f));
    const int gpb = blockIdx.x * MT;
#pragma unroll
    for (int mi = 0; mi < 2; mi++) {
        int mA = m0w + mi * 16 + (lid >> 2);
        int mB = mA + 8;
#pragma unroll
        for (int ng = 0; ng < 8; ng++) {
            int ch = n0w + ng * 8 + (lid & 3) * 2;   // even channel
            int* a4 = acc[mi][ng];
            if (mode == 1) {
                // quantize to levels, pack channel pairs into u16 stores
#pragma unroll
                for (int half = 0; half < 2; half++) {
                    int m = half ? mB : mA;
                    int l01[2];
#pragma unroll
                    for (int e = 0; e < 2; e++) {
                        int cc = ch + e;
                        float v = (float)a4[half * 2 + e] * fac;
                        float y = sBN[cc] * (v - sBN[512 + cc]) * sBN[768 + cc] + sBN[256 + cc];
                        float stp = sBN[1024 + cc];
                        l01[e] = (int)fminf(fmaxf(rintf(y / stp), 0.0f), 15.0f);
                    }
                    outb[(size_t)(ch >> 1) * PADHW + sBase[m]] =
                        (unsigned short)(l01[0] | (l01[1] << 8));
                }
            } else {
#pragma unroll
                for (int e = 0; e < 4; e++) {
                    int cc = ch + (e & 1);
                    int m  = (e < 2) ? mA : mB;
                    float v = (float)a4[e] * fac;
                    if (mode == 0) {
                        outf[(size_t)cc * NPIX + gpb + m] = v;
                    } else {
                        float vv = v + scin[(size_t)cc * NPIX + gpb + m];
                        float y = sBN[cc] * (vv - sBN[512 + cc]) * sBN[768 + cc] + sBN[256 + cc];
                        float stp = sBN[1024 + cc];
                        float q = fminf(fmaxf(rintf(y / stp), 0.0f), 15.0f) * stp;
                        outf[sOb[m] + (size_t)cc * HWSZ] = q;
                    }
                }
            }
        }
    }
}

// ---------------- launch ----------------
extern "C" void kernel_launch(void* const* d_in, const int* in_sizes, int n_in,
                              void* d_out, int out_size) {
    const float* x  = (const float*)d_in[0];
    const float* w1 = (const float*)d_in[1];
    const float* w2 = (const float*)d_in[2];
    const float* ws = (const float*)d_in[3];
    const float* g1 = (const float*)d_in[4];
    const float* b1 = (const float*)d_in[5];
    const float* m1 = (const float*)d_in[6];
    const float* v1 = (const float*)d_in[7];
    const float* s1 = (const float*)d_in[8];
    const float* g2 = (const float*)d_in[9];
    const float* b2 = (const float*)d_in[10];
    const float* m2 = (const float*)d_in[11];
    const float* v2 = (const float*)d_in[12];
    const float* s2 = (const float*)d_in[13];
    float* out = (float*)d_out;

    void* p;
    cudaGetSymbolAddress(&p, g_d0);  unsigned short* d0 = (unsigned short*)p;
    cudaGetSymbolAddress(&p, g_d1);  unsigned short* d1 = (unsigned short*)p;
    cudaGetSymbolAddress(&p, g_d2);  unsigned short* d2 = (unsigned short*)p;
    cudaGetSymbolAddress(&p, g_ri8); unsigned short* ri8 = (unsigned short*)p;
    cudaGetSymbolAddress(&p, g_sc);  float* sc = (float*)p;
    cudaGetSymbolAddress(&p, g_wb1); char* wb1 = (char*)p;
    cudaGetSymbolAddress(&p, g_wb2); char* wb2 = (char*)p;
    cudaGetSymbolAddress(&p, g_wbs); char* wbs = (char*)p;

    cudaFuncSetAttribute(gemm_kernel, cudaFuncAttributeMaxDynamicSharedMemorySize, DSM);

    zero_max_kernel<<<1, 32>>>();
    absmax_kernel<<<148, 256>>>(w1, 256 * 2304, 0);
    absmax_kernel<<<148, 256>>>(w2, 256 * 2304, 1);
    absmax_kernel<<<64,  256>>>(ws, 256 * 256, 2);
    prepw3_kernel<<<2304, 256>>>(w1, wb1, 0);
    prepw3_kernel<<<2304, 256>>>(w2, wb2, 1);
    prepw1_kernel<<<256,  256>>>(ws, wbs, 2);
    splitd_kernel<<<(int)((NPR + 255) / 256), 256>>>(x);

    // shortcut: 1x1, 3 digit phases (2 chunks each) -> g_sc (fp32 planar)
    gemm_kernel<<<NGRID, NTHR, DSM>>>(d0, d1, d2, wbs, 256, 2, 3, 0, 2, 0,
                                      g1, b1, m1, v1, s1, sc, sc, ri8, s1);
    // conv1: 3x3, 3 digit phases (18 chunks each) -> BN1+quant -> ri8 levels
    gemm_kernel<<<NGRID, NTHR, DSM>>>(d0, d1, d2, wb1, 2304, 18, 3, 1, 0, 1,
                                      g1, b1, m1, v1, s1, sc, sc, ri8, s1);
    // conv2: 3x3 on ri8 (exact int) + shortcut -> BN2+quant -> out (fp32 NCHW)
    gemm_kernel<<<NGRID, NTHR, DSM>>>(ri8, ri8, ri8, wb2, 2304, 18, 1, 1, 1, 2,
                                      g2, b2, m2, v2, s2, sc, out, ri8, s1);
}